// round 9
// baseline (speedup 1.0000x reference)
#include <cuda_runtime.h>

#define NBATCH 16
#define NF     128
#define NT     4096
#define NS     4
#define TPB    256
#define PT     16          // TPB*PT == NT
#define GP     20          // padded group stride (16 data + 4 pad floats)
#define BUFSZ  (TPB * GP)  // 5120 floats = 20KB

__device__ __forceinline__ float fast_exp2(float x) {
    float r; asm("ex2.approx.ftz.f32 %0, %1;" : "=f"(r) : "f"(x)); return r;
}
__device__ __forceinline__ float fast_log2(float x) {
    float r; asm("lg2.approx.ftz.f32 %0, %1;" : "=f"(r) : "f"(x)); return r;
}

// Polynomial exp2 for the latency-tolerant final pow: magic-add round +
// deg-4 poly on f in [-0.5,0.5] + exact exponent splice (low 9 bits of
// 0x4B400000 are zero). Valid |t| < 126, max rel err ~4e-5.
__device__ __forceinline__ float poly_exp2(float t) {
    const float magic = 12582912.0f;           // 1.5 * 2^23
    float z  = t + magic;
    float zi = z - magic;
    float fr = t - zi;
    float p  = fmaf(0.00961812911f, fr, 0.05550410866f);
    p = fmaf(p, fr, 0.24022650700f);
    p = fmaf(p, fr, 0.69314718056f);
    p = fmaf(p, fr, 1.0f);
    return __uint_as_float(__float_as_uint(p) + (__float_as_uint(z) << 23));
}

// padded smem float-address of logical element quad Q (elements 4Q..4Q+3)
__device__ __forceinline__ int qaddr(int Q) { return (Q >> 2) * GP + (Q & 3) * 4; }

__global__ __launch_bounds__(TPB, 6)   // force <=42 regs -> 6 blocks/SM (75% occ)
void mrpcen_kernel(const float* __restrict__ x,
                   const float* __restrict__ alpha_log,
                   const float* __restrict__ delta_log,
                   const float* __restrict__ r_log,
                   float* __restrict__ out)
{
    const int row  = blockIdx.x;        // b*NF + f
    const int f    = row & (NF - 1);
    const int b    = row >> 7;
    const int tid  = threadIdx.x;
    const int lane = tid & 31;
    const int w    = tid >> 5;

    __shared__ float buf[2][BUFSZ];
    __shared__ float wagg[NS][TPB / 32];

    // ---- problem-constant smoother coefficients (f32, as in reference) ----
    float s[NS], a[NS];
    {
        const float tv[NS] = {0.015f, 0.06f, 0.25f, 1.0f};
#pragma unroll
        for (int i = 0; i < NS; i++) {
            float tt = tv[i] * (44100.0f / 512.0f);
            float d2 = 2.0f * tt * tt;
            s[i] = (sqrtf(1.0f + 2.0f * d2) - 1.0f) / d2;
            a[i] = 1.0f - s[i];
        }
    }

    const float al    = alpha_log[f];
    const float dl    = delta_log[f];
    const float rl    = r_log[f];
    const float alpha = __expf(al);
    const float delta = __expf(dl);
    const float rr    = __expf(rl);
    const float delta_r = __expf(rr * dl);

    // ---- stage x: coalesced LDG.128 -> padded smem ----
    const float* xrow = x + (size_t)row * NT;
#pragma unroll
    for (int j = 0; j < 4; j++) {
        int Q = j * TPB + tid;
        float4 v = *reinterpret_cast<const float4*>(xrow + 4 * Q);
        *reinterpret_cast<float4*>(&buf[0][qaddr(Q)]) = v;
    }
    __syncthreads();

    // each thread pulls its 16 contiguous elements (own padded group)
    float xv[PT];
#pragma unroll
    for (int q = 0; q < 4; q++) {
        float4 v = *reinterpret_cast<float4*>(&buf[0][tid * GP + q * 4]);
        xv[4 * q + 0] = v.x; xv[4 * q + 1] = v.y;
        xv[4 * q + 2] = v.z; xv[4 * q + 3] = v.w;
    }

    // ---- pass 1 + register scans, all 4 rates ----
    float bc[NS];
#pragma unroll
    for (int si = 0; si < NS; si++) {
        // a^16 recomputed here (pass-1-only) to keep register count down
        float t2 = a[si] * a[si], t4 = t2 * t2, t8 = t4 * t4;
        const float a16 = t8 * t8;
        float bcar = 0.0f;
#pragma unroll
        for (int k = 0; k < PT; k++)
            bcar = fmaf(a[si], bcar, s[si] * xv[k]);
        if (tid == 0)                       // fold m[0]=x[0] boundary (a+s==1)
            bcar = fmaf(a16, xv[0], bcar);
        float c = a16;
#pragma unroll
        for (int d = 1; d <= 16; d <<= 1) {
            float up = __shfl_up_sync(0xffffffffu, bcar, d);
            if (lane >= d) bcar = fmaf(c, up, bcar);
            c = c * c;
        }
        bc[si] = bcar;
        if (lane == 31) wagg[si][w] = bcar;
    }
    __syncthreads();

    // ---- cross-warp: one segmented 32-lane scan handles 4 rates x 8 warps ----
    if (w == 0) {
        const int gsi = lane >> 3, gl = lane & 7;
        float v = wagg[gsi][gl];
        float tt = (gsi == 0) ? (0.015f * (44100.0f / 512.0f)) :
                   (gsi == 1) ? (0.06f  * (44100.0f / 512.0f)) :
                   (gsi == 2) ? (0.25f  * (44100.0f / 512.0f)) :
                                (1.0f   * (44100.0f / 512.0f));
        float d2 = 2.0f * tt * tt;
        float aa = 1.0f - (sqrtf(1.0f + 2.0f * d2) - 1.0f) / d2;
        float c = aa;
#pragma unroll
        for (int i = 0; i < 9; i++) c = c * c;   // a^512
#pragma unroll
        for (int d = 1; d <= 4; d <<= 1) {
            float up = __shfl_up_sync(0xffffffffu, v, d);
            if (gl >= d) v = fmaf(c, up, v);
            c = c * c;
        }
        wagg[gsi][gl] = v;                       // inclusive warp prefix
    }
    __syncthreads();

    // ---- per-thread incoming state for each rate ----
    float minv[NS];
#pragma unroll
    for (int si = 0; si < NS; si++) {
        float Lprev = __shfl_up_sync(0xffffffffu, bc[si], 1);
        if (tid == 0) {
            minv[si] = xv[0];
        } else {
            float P = (w > 0) ? wagg[si][w - 1] : 0.0f;
            float a16l = fast_exp2((float)(16 * lane) * fast_log2(a[si]));
            minv[si] = fmaf(a16l, P, (lane > 0) ? Lprev : 0.0f);
        }
    }

    // ---- pass 2: recurrence + fused PCEN, staged coalesced stores ----
    // final pow -> polynomial exp2 (off the MUFU pipe; latency-tolerant sink)
#pragma unroll
    for (int si = 0; si < NS; si++) {
        float m = minv[si];
        float* sb = buf[si & 1];
#pragma unroll
        for (int q = 0; q < 4; q++) {
            float t4[4];
#pragma unroll
            for (int e = 0; e < 4; e++) {
                const int k = q * 4 + e;
                m = fmaf(a[si], m, s[si] * xv[k]);
                const float u  = 1e-5f + m;                         // eps + m
                const float sm = fast_exp2(-alpha * fast_log2(u));  // (eps+m)^-alpha
                const float v2 = fmaf(xv[k], sm, delta);            // x*smooth + delta
                t4[e] = poly_exp2(rr * fast_log2(v2)) - delta_r;    // v^r - delta^r
            }
            float4 o; o.x = t4[0]; o.y = t4[1]; o.z = t4[2]; o.w = t4[3];
            *reinterpret_cast<float4*>(&sb[tid * GP + q * 4]) = o;  // own group
        }
        __syncthreads();
        float* orow = out + (((size_t)b * NS + si) * NF + f) * (size_t)NT;
#pragma unroll
        for (int j = 0; j < 4; j++) {
            int Q = j * TPB + tid;
            float4 v = *reinterpret_cast<float4*>(&sb[qaddr(Q)]);
            *reinterpret_cast<float4*>(orow + 4 * Q) = v;           // coalesced STG.128
        }
        // double-buffered: next rate writes the other buffer; the next rate's
        // barrier orders this rate's reads before buffer reuse two rates later
    }
}

extern "C" void kernel_launch(void* const* d_in, const int* in_sizes, int n_in,
                              void* d_out, int out_size) {
    const float* x         = (const float*)d_in[0];
    const float* alpha_log = (const float*)d_in[1];
    const float* delta_log = (const float*)d_in[2];
    const float* r_log     = (const float*)d_in[3];
    float* out             = (float*)d_out;
    (void)in_sizes; (void)n_in; (void)out_size;

    dim3 grid(NBATCH * NF);   // 2048 blocks: one per (b, f) row
    dim3 block(TPB);
    mrpcen_kernel<<<grid, block>>>(x, alpha_log, delta_log, r_log, out);
}

// round 10
// speedup vs baseline: 1.0633x; 1.0633x over previous
#include <cuda_runtime.h>

#define NBATCH 16
#define NF     128
#define NT     4096
#define NS     4
#define TPB    256
#define PT     16          // TPB*PT == NT
#define GP     20          // padded group stride (16 data + 4 pad floats)
#define BUFSZ  (TPB * GP)  // 5120 floats = 20KB

__device__ __forceinline__ float fast_exp2(float x) {
    float r; asm("ex2.approx.ftz.f32 %0, %1;" : "=f"(r) : "f"(x)); return r;
}
__device__ __forceinline__ float fast_log2(float x) {
    float r; asm("lg2.approx.ftz.f32 %0, %1;" : "=f"(r) : "f"(x)); return r;
}

// Polynomial exp2 for the latency-tolerant final pow: magic-add round +
// deg-4 poly on f in [-0.5,0.5] + exact exponent splice (low 9 bits of
// 0x4B400000 are zero). Valid |t| < 126, max rel err ~4e-5.
__device__ __forceinline__ float poly_exp2(float t) {
    const float magic = 12582912.0f;           // 1.5 * 2^23
    float z  = t + magic;
    float zi = z - magic;
    float fr = t - zi;
    float p  = fmaf(0.00961812911f, fr, 0.05550410866f);
    p = fmaf(p, fr, 0.24022650700f);
    p = fmaf(p, fr, 0.69314718056f);
    p = fmaf(p, fr, 1.0f);
    return __uint_as_float(__float_as_uint(p) + (__float_as_uint(z) << 23));
}

// padded smem float-address of logical element quad Q (elements 4Q..4Q+3)
__device__ __forceinline__ int qaddr(int Q) { return (Q >> 2) * GP + (Q & 3) * 4; }

__global__ __launch_bounds__(TPB, 6)   // 6 blocks/SM: regs<=42, smem ~21KB
void mrpcen_kernel(const float* __restrict__ x,
                   const float* __restrict__ alpha_log,
                   const float* __restrict__ delta_log,
                   const float* __restrict__ r_log,
                   float* __restrict__ out)
{
    const int row  = blockIdx.x;        // b*NF + f
    const int f    = row & (NF - 1);
    const int b    = row >> 7;
    const int tid  = threadIdx.x;
    const int lane = tid & 31;
    const int w    = tid >> 5;

    __shared__ float buf[BUFSZ];        // single 20KB staging buffer
    __shared__ float wagg[NS][TPB / 32];

    // ---- problem-constant smoother coefficients (f32, as in reference) ----
    float s[NS], a[NS];
    {
        const float tv[NS] = {0.015f, 0.06f, 0.25f, 1.0f};
#pragma unroll
        for (int i = 0; i < NS; i++) {
            float tt = tv[i] * (44100.0f / 512.0f);
            float d2 = 2.0f * tt * tt;
            s[i] = (sqrtf(1.0f + 2.0f * d2) - 1.0f) / d2;
            a[i] = 1.0f - s[i];
        }
    }

    const float al    = alpha_log[f];
    const float dl    = delta_log[f];
    const float rl    = r_log[f];
    const float alpha = __expf(al);
    const float delta = __expf(dl);
    const float rr    = __expf(rl);
    const float delta_r = __expf(rr * dl);

    // ---- stage x: coalesced LDG.128 -> padded smem ----
    const float* xrow = x + (size_t)row * NT;
#pragma unroll
    for (int j = 0; j < 4; j++) {
        int Q = j * TPB + tid;
        float4 v = *reinterpret_cast<const float4*>(xrow + 4 * Q);
        *reinterpret_cast<float4*>(&buf[qaddr(Q)]) = v;
    }
    __syncthreads();

    // each thread pulls its 16 contiguous elements (own padded group)
    float xv[PT];
#pragma unroll
    for (int q = 0; q < 4; q++) {
        float4 v = *reinterpret_cast<float4*>(&buf[tid * GP + q * 4]);
        xv[4 * q + 0] = v.x; xv[4 * q + 1] = v.y;
        xv[4 * q + 2] = v.z; xv[4 * q + 3] = v.w;
    }

    // ---- pass 1 + register scans, all 4 rates ----
    float bc[NS];
#pragma unroll
    for (int si = 0; si < NS; si++) {
        // a^16 recomputed here (pass-1-only) to keep register count down
        float t2 = a[si] * a[si], t4 = t2 * t2, t8 = t4 * t4;
        const float a16 = t8 * t8;
        float bcar = 0.0f;
#pragma unroll
        for (int k = 0; k < PT; k++)
            bcar = fmaf(a[si], bcar, s[si] * xv[k]);
        if (tid == 0)                       // fold m[0]=x[0] boundary (a+s==1)
            bcar = fmaf(a16, xv[0], bcar);
        float c = a16;
#pragma unroll
        for (int d = 1; d <= 16; d <<= 1) {
            float up = __shfl_up_sync(0xffffffffu, bcar, d);
            if (lane >= d) bcar = fmaf(c, up, bcar);
            c = c * c;
        }
        bc[si] = bcar;
        if (lane == 31) wagg[si][w] = bcar;
    }
    __syncthreads();

    // ---- cross-warp: one segmented 32-lane scan handles 4 rates x 8 warps ----
    if (w == 0) {
        const int gsi = lane >> 3, gl = lane & 7;
        float v = wagg[gsi][gl];
        float tt = (gsi == 0) ? (0.015f * (44100.0f / 512.0f)) :
                   (gsi == 1) ? (0.06f  * (44100.0f / 512.0f)) :
                   (gsi == 2) ? (0.25f  * (44100.0f / 512.0f)) :
                                (1.0f   * (44100.0f / 512.0f));
        float d2 = 2.0f * tt * tt;
        float aa = 1.0f - (sqrtf(1.0f + 2.0f * d2) - 1.0f) / d2;
        float c = aa;
#pragma unroll
        for (int i = 0; i < 9; i++) c = c * c;   // a^512
#pragma unroll
        for (int d = 1; d <= 4; d <<= 1) {
            float up = __shfl_up_sync(0xffffffffu, v, d);
            if (gl >= d) v = fmaf(c, up, v);
            c = c * c;
        }
        wagg[gsi][gl] = v;                       // inclusive warp prefix
    }
    __syncthreads();

    // ---- per-thread incoming state for each rate ----
    float minv[NS];
#pragma unroll
    for (int si = 0; si < NS; si++) {
        float Lprev = __shfl_up_sync(0xffffffffu, bc[si], 1);
        if (tid == 0) {
            minv[si] = xv[0];
        } else {
            float P = (w > 0) ? wagg[si][w - 1] : 0.0f;
            float a16l = fast_exp2((float)(16 * lane) * fast_log2(a[si]));
            minv[si] = fmaf(a16l, P, (lane > 0) ? Lprev : 0.0f);
        }
    }

    // ---- pass 2: recurrence + fused PCEN, single-buffer staged stores ----
    // final pow -> polynomial exp2 (off the MUFU pipe; latency-tolerant sink)
#pragma unroll
    for (int si = 0; si < NS; si++) {
        float m = minv[si];
#pragma unroll
        for (int q = 0; q < 4; q++) {
            float t4[4];
#pragma unroll
            for (int e = 0; e < 4; e++) {
                const int k = q * 4 + e;
                m = fmaf(a[si], m, s[si] * xv[k]);
                const float u  = 1e-5f + m;                         // eps + m
                const float sm = fast_exp2(-alpha * fast_log2(u));  // (eps+m)^-alpha
                const float v2 = fmaf(xv[k], sm, delta);            // x*smooth + delta
                t4[e] = poly_exp2(rr * fast_log2(v2)) - delta_r;    // v^r - delta^r
            }
            float4 o; o.x = t4[0]; o.y = t4[1]; o.z = t4[2]; o.w = t4[3];
            *reinterpret_cast<float4*>(&buf[tid * GP + q * 4]) = o; // own group
        }
        __syncthreads();                       // writes visible before drain
        float* orow = out + (((size_t)b * NS + si) * NF + f) * (size_t)NT;
#pragma unroll
        for (int j = 0; j < 4; j++) {
            int Q = j * TPB + tid;
            float4 v = *reinterpret_cast<float4*>(&buf[qaddr(Q)]);
            *reinterpret_cast<float4*>(orow + 4 * Q) = v;           // coalesced STG.128
        }
        if (si < NS - 1) __syncthreads();      // drain done before buffer reuse
    }
}

extern "C" void kernel_launch(void* const* d_in, const int* in_sizes, int n_in,
                              void* d_out, int out_size) {
    const float* x         = (const float*)d_in[0];
    const float* alpha_log = (const float*)d_in[1];
    const float* delta_log = (const float*)d_in[2];
    const float* r_log     = (const float*)d_in[3];
    float* out             = (float*)d_out;
    (void)in_sizes; (void)n_in; (void)out_size;

    dim3 grid(NBATCH * NF);   // 2048 blocks: one per (b, f) row
    dim3 block(TPB);
    mrpcen_kernel<<<grid, block>>>(x, alpha_log, delta_log, r_log, out);
}

// round 11
// speedup vs baseline: 1.0959x; 1.0306x over previous
#include <cuda_runtime.h>

#define NBATCH 16
#define NF     128
#define NT     4096
#define NS     4
#define TPB    256
#define PT     16          // TPB*PT == NT
#define GP     20          // padded group stride (16 data + 4 pad floats)
#define BUFSZ  (TPB * GP)  // 5120 floats = 20KB

__device__ __forceinline__ float fast_exp2(float x) {
    float r; asm("ex2.approx.ftz.f32 %0, %1;" : "=f"(r) : "f"(x)); return r;
}
__device__ __forceinline__ float fast_log2(float x) {
    float r; asm("lg2.approx.ftz.f32 %0, %1;" : "=f"(r) : "f"(x)); return r;
}

// padded smem float-address of logical element quad Q (elements 4Q..4Q+3)
__device__ __forceinline__ int qaddr(int Q) { return (Q >> 2) * GP + (Q & 3) * 4; }

__global__ __launch_bounds__(TPB, 6)   // 6 blocks/SM: regs<=42, smem ~21KB
void mrpcen_kernel(const float* __restrict__ x,
                   const float* __restrict__ alpha_log,
                   const float* __restrict__ delta_log,
                   const float* __restrict__ r_log,
                   float* __restrict__ out)
{
    const int row  = blockIdx.x;        // b*NF + f
    const int f    = row & (NF - 1);
    const int b    = row >> 7;
    const int tid  = threadIdx.x;
    const int lane = tid & 31;
    const int w    = tid >> 5;

    __shared__ float buf[BUFSZ];        // single 20KB staging buffer
    __shared__ float wagg[NS][TPB / 32];

    // ---- problem-constant smoother coefficients (f32, as in reference) ----
    float s[NS], a[NS];
    {
        const float tv[NS] = {0.015f, 0.06f, 0.25f, 1.0f};
#pragma unroll
        for (int i = 0; i < NS; i++) {
            float tt = tv[i] * (44100.0f / 512.0f);
            float d2 = 2.0f * tt * tt;
            s[i] = (sqrtf(1.0f + 2.0f * d2) - 1.0f) / d2;
            a[i] = 1.0f - s[i];
        }
    }

    const float al    = alpha_log[f];
    const float dl    = delta_log[f];
    const float rl    = r_log[f];
    const float alpha = __expf(al);
    const float delta = __expf(dl);
    const float rr    = __expf(rl);
    const float delta_r = __expf(rr * dl);

    // ---- stage x: coalesced LDG.128 -> padded smem ----
    const float* xrow = x + (size_t)row * NT;
#pragma unroll
    for (int j = 0; j < 4; j++) {
        int Q = j * TPB + tid;
        float4 v = *reinterpret_cast<const float4*>(xrow + 4 * Q);
        *reinterpret_cast<float4*>(&buf[qaddr(Q)]) = v;
    }
    __syncthreads();

    // each thread pulls its 16 contiguous elements (own padded group)
    float xv[PT];
#pragma unroll
    for (int q = 0; q < 4; q++) {
        float4 v = *reinterpret_cast<float4*>(&buf[tid * GP + q * 4]);
        xv[4 * q + 0] = v.x; xv[4 * q + 1] = v.y;
        xv[4 * q + 2] = v.z; xv[4 * q + 3] = v.w;
    }

    // ---- pass 1 + register scans, all 4 rates ----
    float bc[NS];
#pragma unroll
    for (int si = 0; si < NS; si++) {
        // a^16 recomputed here (pass-1-only) to keep register count down
        float t2 = a[si] * a[si], t4 = t2 * t2, t8 = t4 * t4;
        const float a16 = t8 * t8;
        float bcar = 0.0f;
#pragma unroll
        for (int k = 0; k < PT; k++)
            bcar = fmaf(a[si], bcar, s[si] * xv[k]);
        if (tid == 0)                       // fold m[0]=x[0] boundary (a+s==1)
            bcar = fmaf(a16, xv[0], bcar);
        float c = a16;
#pragma unroll
        for (int d = 1; d <= 16; d <<= 1) {
            float up = __shfl_up_sync(0xffffffffu, bcar, d);
            if (lane >= d) bcar = fmaf(c, up, bcar);
            c = c * c;
        }
        bc[si] = bcar;
        if (lane == 31) wagg[si][w] = bcar;
    }
    __syncthreads();

    // ---- cross-warp: one segmented 32-lane scan handles 4 rates x 8 warps ----
    if (w == 0) {
        const int gsi = lane >> 3, gl = lane & 7;
        float v = wagg[gsi][gl];
        float tt = (gsi == 0) ? (0.015f * (44100.0f / 512.0f)) :
                   (gsi == 1) ? (0.06f  * (44100.0f / 512.0f)) :
                   (gsi == 2) ? (0.25f  * (44100.0f / 512.0f)) :
                                (1.0f   * (44100.0f / 512.0f));
        float d2 = 2.0f * tt * tt;
        float aa = 1.0f - (sqrtf(1.0f + 2.0f * d2) - 1.0f) / d2;
        float c = aa;
#pragma unroll
        for (int i = 0; i < 9; i++) c = c * c;   // a^512
#pragma unroll
        for (int d = 1; d <= 4; d <<= 1) {
            float up = __shfl_up_sync(0xffffffffu, v, d);
            if (gl >= d) v = fmaf(c, up, v);
            c = c * c;
        }
        wagg[gsi][gl] = v;                       // inclusive warp prefix
    }
    __syncthreads();

    // ---- per-thread incoming state for each rate ----
    float minv[NS];
#pragma unroll
    for (int si = 0; si < NS; si++) {
        float Lprev = __shfl_up_sync(0xffffffffu, bc[si], 1);
        if (tid == 0) {
            minv[si] = xv[0];
        } else {
            float P = (w > 0) ? wagg[si][w - 1] : 0.0f;
            float a16l = fast_exp2((float)(16 * lane) * fast_log2(a[si]));
            minv[si] = fmaf(a16l, P, (lane > 0) ? Lprev : 0.0f);
        }
    }

    // ---- pass 2: recurrence + fused PCEN (pure MUFU), staged stores ----
#pragma unroll
    for (int si = 0; si < NS; si++) {
        float m = minv[si];
#pragma unroll
        for (int q = 0; q < 4; q++) {
            float t4[4];
#pragma unroll
            for (int e = 0; e < 4; e++) {
                const int k = q * 4 + e;
                m = fmaf(a[si], m, s[si] * xv[k]);
                const float u  = 1e-5f + m;                         // eps + m
                const float sm = fast_exp2(-alpha * fast_log2(u));  // (eps+m)^-alpha
                const float v2 = fmaf(xv[k], sm, delta);            // x*smooth + delta
                t4[e] = fast_exp2(rr * fast_log2(v2)) - delta_r;    // v^r - delta^r
            }
            float4 o; o.x = t4[0]; o.y = t4[1]; o.z = t4[2]; o.w = t4[3];
            *reinterpret_cast<float4*>(&buf[tid * GP + q * 4]) = o; // own group
        }
        __syncthreads();                       // writes visible before drain
        float* orow = out + (((size_t)b * NS + si) * NF + f) * (size_t)NT;
#pragma unroll
        for (int j = 0; j < 4; j++) {
            int Q = j * TPB + tid;
            float4 v = *reinterpret_cast<float4*>(&buf[qaddr(Q)]);
            *reinterpret_cast<float4*>(orow + 4 * Q) = v;           // coalesced STG.128
        }
        if (si < NS - 1) __syncthreads();      // drain done before buffer reuse
    }
}

extern "C" void kernel_launch(void* const* d_in, const int* in_sizes, int n_in,
                              void* d_out, int out_size) {
    const float* x         = (const float*)d_in[0];
    const float* alpha_log = (const float*)d_in[1];
    const float* delta_log = (const float*)d_in[2];
    const float* r_log     = (const float*)d_in[3];
    float* out             = (float*)d_out;
    (void)in_sizes; (void)n_in; (void)out_size;

    dim3 grid(NBATCH * NF);   // 2048 blocks: one per (b, f) row
    dim3 block(TPB);
    mrpcen_kernel<<<grid, block>>>(x, alpha_log, delta_log, r_log, out);
}

// round 12
// speedup vs baseline: 1.2443x; 1.1354x over previous
#include <cuda_runtime.h>

#define NBATCH 16
#define NF     128
#define NT     4096
#define NS     4
#define TPB    256
#define PT     16          // TPB*PT == NT
#define GP     20          // padded group stride (16 data + 4 pad floats)
#define WSLAB  (32 * GP)   // per-warp slab: 640 floats = 2.5KB
#define BUFSZ  (8 * WSLAB) // 5120 floats = 20KB

__device__ __forceinline__ float fast_exp2(float x) {
    float r; asm("ex2.approx.ftz.f32 %0, %1;" : "=f"(r) : "f"(x)); return r;
}
__device__ __forceinline__ float fast_log2(float x) {
    float r; asm("lg2.approx.ftz.f32 %0, %1;" : "=f"(r) : "f"(x)); return r;
}

__global__ __launch_bounds__(TPB, 6)
void mrpcen_kernel(const float* __restrict__ x,
                   const float* __restrict__ alpha_log,
                   const float* __restrict__ delta_log,
                   const float* __restrict__ r_log,
                   float* __restrict__ out)
{
    const int row  = blockIdx.x;        // b*NF + f
    const int f    = row & (NF - 1);
    const int b    = row >> 7;
    const int tid  = threadIdx.x;
    const int lane = tid & 31;
    const int w    = tid >> 5;

    __shared__ float buf[BUFSZ];        // 8 private per-warp slabs
    __shared__ float wagg[NS][TPB / 32];

    float* slab = &buf[w * WSLAB];

    // ---- problem-constant smoother coefficients (f32, as in reference) ----
    float s[NS], a[NS];
    {
        const float tv[NS] = {0.015f, 0.06f, 0.25f, 1.0f};
#pragma unroll
        for (int i = 0; i < NS; i++) {
            float tt = tv[i] * (44100.0f / 512.0f);
            float d2 = 2.0f * tt * tt;
            s[i] = (sqrtf(1.0f + 2.0f * d2) - 1.0f) / d2;
            a[i] = 1.0f - s[i];
        }
    }

    const float al    = alpha_log[f];
    const float dl    = delta_log[f];
    const float rl    = r_log[f];
    const float alpha = __expf(al);
    const float delta = __expf(dl);
    const float rr    = __expf(rl);
    const float delta_r = __expf(rr * dl);

    // ---- per-warp x staging: coalesced LDG.128 -> own slab (no block barrier) ----
    const float* xrow = x + (size_t)row * NT + (size_t)w * 512;
#pragma unroll
    for (int j = 0; j < 4; j++) {
        int Q = j * 32 + lane;               // local quad index within warp slice
        float4 v = *reinterpret_cast<const float4*>(xrow + 4 * Q);
        *reinterpret_cast<float4*>(&slab[(Q >> 2) * GP + (Q & 3) * 4]) = v;
    }
    __syncwarp();

    // each thread pulls its 16 contiguous elements (own padded group)
    float xv[PT];
#pragma unroll
    for (int q = 0; q < 4; q++) {
        float4 v = *reinterpret_cast<float4*>(&slab[lane * GP + q * 4]);
        xv[4 * q + 0] = v.x; xv[4 * q + 1] = v.y;
        xv[4 * q + 2] = v.z; xv[4 * q + 3] = v.w;
    }

    // ---- pass 1 + warp register scans, all 4 rates ----
    float bc[NS];
#pragma unroll
    for (int si = 0; si < NS; si++) {
        float t2 = a[si] * a[si], t4 = t2 * t2, t8 = t4 * t4;
        const float a16 = t8 * t8;
        float bcar = 0.0f;
#pragma unroll
        for (int k = 0; k < PT; k++)
            bcar = fmaf(a[si], bcar, s[si] * xv[k]);
        if (tid == 0)                       // fold m[0]=x[0] boundary (a+s==1)
            bcar = fmaf(a16, xv[0], bcar);
        float c = a16;
#pragma unroll
        for (int d = 1; d <= 16; d <<= 1) {
            float up = __shfl_up_sync(0xffffffffu, bcar, d);
            if (lane >= d) bcar = fmaf(c, up, bcar);
            c = c * c;
        }
        bc[si] = bcar;
        if (lane == 31) wagg[si][w] = bcar;
    }
    __syncthreads();                         // scan barrier #1

    // ---- cross-warp: one segmented 32-lane scan handles 4 rates x 8 warps ----
    if (w == 0) {
        const int gsi = lane >> 3, gl = lane & 7;
        float v = wagg[gsi][gl];
        float tt = (gsi == 0) ? (0.015f * (44100.0f / 512.0f)) :
                   (gsi == 1) ? (0.06f  * (44100.0f / 512.0f)) :
                   (gsi == 2) ? (0.25f  * (44100.0f / 512.0f)) :
                                (1.0f   * (44100.0f / 512.0f));
        float d2 = 2.0f * tt * tt;
        float aa = 1.0f - (sqrtf(1.0f + 2.0f * d2) - 1.0f) / d2;
        float c = aa;
#pragma unroll
        for (int i = 0; i < 9; i++) c = c * c;   // a^512
#pragma unroll
        for (int d = 1; d <= 4; d <<= 1) {
            float up = __shfl_up_sync(0xffffffffu, v, d);
            if (gl >= d) v = fmaf(c, up, v);
            c = c * c;
        }
        wagg[gsi][gl] = v;                       // inclusive warp prefix
    }
    __syncthreads();                         // scan barrier #2 (last block barrier)

    // ---- per-thread incoming state for each rate ----
    float minv[NS];
#pragma unroll
    for (int si = 0; si < NS; si++) {
        float Lprev = __shfl_up_sync(0xffffffffu, bc[si], 1);
        if (tid == 0) {
            minv[si] = xv[0];
        } else {
            float P = (w > 0) ? wagg[si][w - 1] : 0.0f;
            float a16l = fast_exp2((float)(16 * lane) * fast_log2(a[si]));
            minv[si] = fmaf(a16l, P, (lane > 0) ? Lprev : 0.0f);
        }
    }

    // ---- pass 2: per-warp barrier-free pipeline over 4 rates ----
    float* orow0 = out + (((size_t)b * NS) * NF + f) * (size_t)NT + (size_t)w * 512;
#pragma unroll
    for (int si = 0; si < NS; si++) {
        float m = minv[si];
#pragma unroll
        for (int q = 0; q < 4; q++) {
            float t4[4];
#pragma unroll
            for (int e = 0; e < 4; e++) {
                const int k = q * 4 + e;
                m = fmaf(a[si], m, s[si] * xv[k]);
                const float u  = 1e-5f + m;                         // eps + m
                const float sm = fast_exp2(-alpha * fast_log2(u));  // (eps+m)^-alpha
                const float v2 = fmaf(xv[k], sm, delta);            // x*smooth + delta
                t4[e] = fast_exp2(rr * fast_log2(v2)) - delta_r;    // v^r - delta^r
            }
            float4 o; o.x = t4[0]; o.y = t4[1]; o.z = t4[2]; o.w = t4[3];
            *reinterpret_cast<float4*>(&slab[lane * GP + q * 4]) = o;
        }
        __syncwarp();                        // slab writes visible within warp
        float* orow = orow0 + (size_t)si * (NF * NT);
#pragma unroll
        for (int j = 0; j < 4; j++) {
            int Q = j * 32 + lane;
            float4 v = *reinterpret_cast<float4*>(&slab[(Q >> 2) * GP + (Q & 3) * 4]);
            *reinterpret_cast<float4*>(orow + 4 * Q) = v;           // coalesced STG.128
        }
        if (si < NS - 1) __syncwarp();       // drain done before slab reuse
    }
}

extern "C" void kernel_launch(void* const* d_in, const int* in_sizes, int n_in,
                              void* d_out, int out_size) {
    const float* x         = (const float*)d_in[0];
    const float* alpha_log = (const float*)d_in[1];
    const float* delta_log = (const float*)d_in[2];
    const float* r_log     = (const float*)d_in[3];
    float* out             = (float*)d_out;
    (void)in_sizes; (void)n_in; (void)out_size;

    dim3 grid(NBATCH * NF);   // 2048 blocks: one per (b, f) row
    dim3 block(TPB);
    mrpcen_kernel<<<grid, block>>>(x, alpha_log, delta_log, r_log, out);
}